// round 14
// baseline (speedup 1.0000x reference)
#include <cuda_runtime.h>
#include <cuda_bf16.h>
#include <stdint.h>

#define C_    384
#define NH_   12
#define HD_   32
#define P_    49
#define BW_   2048
#define TOK_  100352
#define QKVN_ 1152
#define NKC_  24
#define NMT_  (TOK_ / 16)   // 6272 m-tiles

#define WQKV_FSZ (72 * NKC_ * 32 * 8)
#define WOUT_FSZ (24 * NKC_ * 32 * 8)
#define AF_SZ    (NMT_ * NKC_ * 32 * 8)   // 38.5M bf16

__device__ float g_attn[TOK_ * C_];
__device__ __nv_bfloat16 g_qh[BW_ * NH_ * P_ * HD_];
__device__ __nv_bfloat16 g_ql[BW_ * NH_ * P_ * HD_];
__device__ __nv_bfloat16 g_kh[BW_ * NH_ * P_ * HD_];
__device__ __nv_bfloat16 g_kl[BW_ * NH_ * P_ * HD_];
__device__ __nv_bfloat16 g_vh[BW_ * NH_ * P_ * HD_];
__device__ __nv_bfloat16 g_vl[BW_ * NH_ * P_ * HD_];
__device__ __nv_bfloat16 g_wqkvFh[WQKV_FSZ];
__device__ __nv_bfloat16 g_wqkvFl[WQKV_FSZ];
__device__ __nv_bfloat16 g_woutFh[WOUT_FSZ];
__device__ __nv_bfloat16 g_woutFl[WOUT_FSZ];
__device__ __nv_bfloat16 g_xFh[AF_SZ];
__device__ __nv_bfloat16 g_xFl[AF_SZ];
__device__ __nv_bfloat16 g_aFh[AF_SZ];
__device__ __nv_bfloat16 g_aFl[AF_SZ];

__device__ __forceinline__ int token_to_xoff(int t) {
    int b  = t / 3136;
    int r  = t - b * 3136;
    int w  = r / 49;
    int pp = r - w * 49;
    int wi = w >> 3, wj = w & 7;
    int pi = pp / 7, pj = pp - pi * 7;
    return ((b * 56 + wi * 7 + pi) * 56 + (wj * 7 + pj)) * 384;
}

__device__ __forceinline__ uint32_t pack_hi2(float x, float y) {
    __nv_bfloat16 hx = __float2bfloat16(x);
    __nv_bfloat16 hy = __float2bfloat16(y);
    return (uint32_t)__bfloat16_as_ushort(hx) | ((uint32_t)__bfloat16_as_ushort(hy) << 16);
}
__device__ __forceinline__ uint32_t pack_lo2(float x, float y) {
    __nv_bfloat16 hx = __float2bfloat16(x);
    __nv_bfloat16 hy = __float2bfloat16(y);
    __nv_bfloat16 lx = __float2bfloat16(x - __bfloat162float(hx));
    __nv_bfloat16 ly = __float2bfloat16(y - __bfloat162float(hy));
    return (uint32_t)__bfloat16_as_ushort(lx) | ((uint32_t)__bfloat16_as_ushort(ly) << 16);
}

// ---------------------------------------------------------------------------
// prep: weights (proven R8/R13 layout)
// ---------------------------------------------------------------------------
__global__ void prep_wF(const float* __restrict__ wqkv, const float* __restrict__ wout) {
    const int idx = blockIdx.x * 256 + threadIdx.x;
    if (idx < WQKV_FSZ) {
        const int j = idx & 7;
        int tmp = idx >> 3;
        const int lane = tmp & 31;
        tmp >>= 5;
        const int kc = tmp % NKC_;
        const int ng = tmp / NKC_;
        const int pr = j >> 2;
        const int rg = (j >> 1) & 1;
        const int je = j & 1;
        const int n = ng * 16 + (lane >> 2) + pr * 8;
        const int k = kc * 16 + rg * 8 + (lane & 3) * 2 + je;
        const float v = wqkv[k * QKVN_ + n];
        const __nv_bfloat16 h = __float2bfloat16(v);
        g_wqkvFh[idx] = h;
        g_wqkvFl[idx] = __float2bfloat16(v - __bfloat162float(h));
    } else {
        const int i2 = idx - WQKV_FSZ;
        if (i2 < WOUT_FSZ) {
            const int j = i2 & 7;
            int tmp = i2 >> 3;
            const int lane = tmp & 31;
            tmp >>= 5;
            const int kc = tmp % NKC_;
            const int ng = tmp / NKC_;
            const int pr = j >> 2;
            const int rg = (j >> 1) & 1;
            const int je = j & 1;
            const int n = ng * 16 + (lane >> 2) + pr * 8;
            const int k = kc * 16 + rg * 8 + (lane & 3) * 2 + je;
            const float v = wout[k * C_ + n];
            const __nv_bfloat16 h = __float2bfloat16(v);
            g_woutFh[i2] = h;
            g_woutFl[i2] = __float2bfloat16(v - __bfloat162float(h));
        }
    }
}

// ---------------------------------------------------------------------------
// prep: x -> A-fragments. One thread per [mt][kc][lane] writes uint4 hi + lo.
// A-frag per lane: reg0=(t0, 2c,2c+1) reg1=(t1, 2c,2c+1) reg2=(t0, 8+2c,..)
// reg3=(t1, 8+2c,..) where t0 = mt*16+gid, t1 = t0+8.
// ---------------------------------------------------------------------------
__global__ void prep_xF(const float* __restrict__ x) {
    const int idx = blockIdx.x * 256 + threadIdx.x;   // NMT_*NKC_*32 = 4,816,896
    const int lane = idx & 31;
    int tmp = idx >> 5;
    const int kc = tmp % NKC_;
    const int mt = tmp / NKC_;
    const int gid = lane >> 2;
    const int ctid = lane & 3;
    const int t0 = mt * 16 + gid;
    const int t1 = t0 + 8;
    const int kb = kc * 16 + 2 * ctid;
    const float* p0 = x + token_to_xoff(t0);
    const float* p1 = x + token_to_xoff(t1);
    const float2 v0 = *(const float2*)(p0 + kb);
    const float2 v1 = *(const float2*)(p1 + kb);
    const float2 v2 = *(const float2*)(p0 + kb + 8);
    const float2 v3 = *(const float2*)(p1 + kb + 8);
    uint4 H;
    uint4 L;
    H.x = pack_hi2(v0.x, v0.y); L.x = pack_lo2(v0.x, v0.y);
    H.y = pack_hi2(v1.x, v1.y); L.y = pack_lo2(v1.x, v1.y);
    H.z = pack_hi2(v2.x, v2.y); L.z = pack_lo2(v2.x, v2.y);
    H.w = pack_hi2(v3.x, v3.y); L.w = pack_lo2(v3.x, v3.y);
    *(uint4*)&g_xFh[(size_t)idx * 8] = H;
    *(uint4*)&g_xFl[(size_t)idx * 8] = L;
}

// prep: g_attn (token-major fp32) -> A-fragments for proj
__global__ void prep_aF() {
    const int idx = blockIdx.x * 256 + threadIdx.x;
    const int lane = idx & 31;
    int tmp = idx >> 5;
    const int kc = tmp % NKC_;
    const int mt = tmp / NKC_;
    const int gid = lane >> 2;
    const int ctid = lane & 3;
    const int t0 = mt * 16 + gid;
    const int t1 = t0 + 8;
    const int kb = kc * 16 + 2 * ctid;
    const float* p0 = g_attn + (size_t)t0 * C_;
    const float* p1 = g_attn + (size_t)t1 * C_;
    const float2 v0 = *(const float2*)(p0 + kb);
    const float2 v1 = *(const float2*)(p1 + kb);
    const float2 v2 = *(const float2*)(p0 + kb + 8);
    const float2 v3 = *(const float2*)(p1 + kb + 8);
    uint4 H;
    uint4 L;
    H.x = pack_hi2(v0.x, v0.y); L.x = pack_lo2(v0.x, v0.y);
    H.y = pack_hi2(v1.x, v1.y); L.y = pack_lo2(v1.x, v1.y);
    H.z = pack_hi2(v2.x, v2.y); L.z = pack_lo2(v2.x, v2.y);
    H.w = pack_hi2(v3.x, v3.y); L.w = pack_lo2(v3.x, v3.y);
    *(uint4*)&g_aFh[(size_t)idx * 8] = H;
    *(uint4*)&g_aFl[(size_t)idx * 8] = L;
}

__device__ __forceinline__ void mma16816(float* c, const uint32_t* a, const uint32_t* b) {
    asm volatile("mma.sync.aligned.m16n8k16.row.col.f32.bf16.bf16.f32 "
                 "{%0,%1,%2,%3}, {%4,%5,%6,%7}, {%8,%9}, {%0,%1,%2,%3};"
                 : "+f"(c[0]), "+f"(c[1]), "+f"(c[2]), "+f"(c[3])
                 : "r"(a[0]), "r"(a[1]), "r"(a[2]), "r"(a[3]), "r"(b[0]), "r"(b[1]));
}

__device__ __forceinline__ void scatter_qkv_bf(int w, int pp, int n, float vx, float vy) {
    int which = n / C_;
    int nn = n - which * C_;
    int head = nn >> 5;
    int d = nn & 31;
    __nv_bfloat16* dh;
    __nv_bfloat16* dl;
    if (which == 0)      { dh = g_qh; dl = g_ql; }
    else if (which == 1) { dh = g_kh; dl = g_kl; }
    else                 { dh = g_vh; dl = g_vl; }
    int off = ((w * NH_ + head) * P_ + pp) * HD_ + d;
    *(uint32_t*)&dh[off] = pack_hi2(vx, vy);
    *(uint32_t*)&dl[off] = pack_lo2(vx, vy);
}

#define BM 128
#define BN 128

// ---------------------------------------------------------------------------
// Smem-free GEMM: pure LDG (A+B fragments from L2/L1) + MMA. No barriers.
// ---------------------------------------------------------------------------
__global__ __launch_bounds__(256) void qkv_mma(const float* __restrict__ bias) {
    const int tid = threadIdx.x;
    const int n0 = blockIdx.x * BN;   // n fastest
    const int m0 = blockIdx.y * BM;

    const int warp = tid >> 5;
    const int lane = tid & 31;
    const int wm = (warp >> 2) * 64;
    const int wn = (warp & 3) * 32;

    const int mt0 = (m0 + wm) >> 4;
    const __nv_bfloat16* aH = g_xFh + ((size_t)mt0 * NKC_) * 256 + lane * 8;
    const __nv_bfloat16* aL = g_xFl + ((size_t)mt0 * NKC_) * 256 + lane * 8;

    const int ng0 = (n0 + wn) >> 4;
    const __nv_bfloat16* bH = g_wqkvFh + (size_t)ng0 * 6144 + lane * 8;
    const __nv_bfloat16* bL = g_wqkvFl + (size_t)ng0 * 6144 + lane * 8;

    float acc[4][4][4];
#pragma unroll
    for (int i = 0; i < 4; i++)
#pragma unroll
        for (int j = 0; j < 4; j++)
#pragma unroll
            for (int e = 0; e < 4; e++) acc[i][j][e] = 0.f;

#pragma unroll 4
    for (int kt = 0; kt < NKC_; kt++) {
        uint4 ahv[4];
        uint4 alv[4];
#pragma unroll
        for (int i = 0; i < 4; i++) {
            ahv[i] = *(const uint4*)(aH + ((size_t)i * NKC_ + kt) * 256);
            alv[i] = *(const uint4*)(aL + ((size_t)i * NKC_ + kt) * 256);
        }
        const uint4 bh01 = *(const uint4*)(bH + kt * 256);
        const uint4 bh23 = *(const uint4*)(bH + 6144 + kt * 256);
        const uint4 bl01 = *(const uint4*)(bL + kt * 256);
        const uint4 bl23 = *(const uint4*)(bL + 6144 + kt * 256);
        uint32_t bh[4][2];
        uint32_t bl[4][2];
        bh[0][0] = bh01.x; bh[0][1] = bh01.y;
        bh[1][0] = bh01.z; bh[1][1] = bh01.w;
        bh[2][0] = bh23.x; bh[2][1] = bh23.y;
        bh[3][0] = bh23.z; bh[3][1] = bh23.w;
        bl[0][0] = bl01.x; bl[0][1] = bl01.y;
        bl[1][0] = bl01.z; bl[1][1] = bl01.w;
        bl[2][0] = bl23.x; bl[2][1] = bl23.y;
        bl[3][0] = bl23.z; bl[3][1] = bl23.w;

#pragma unroll
        for (int i = 0; i < 4; i++) {
            const uint32_t* ah = (const uint32_t*)&ahv[i];
            const uint32_t* al = (const uint32_t*)&alv[i];
#pragma unroll
            for (int j = 0; j < 4; j++) {
                mma16816(acc[i][j], ah, bh[j]);
                mma16816(acc[i][j], ah, bl[j]);
                mma16816(acc[i][j], al, bh[j]);
            }
        }
    }

    const int gid = lane >> 2;
    const int ctid = lane & 3;
#pragma unroll
    for (int i = 0; i < 4; i++) {
        const int r0 = m0 + wm + i * 16 + gid;
        const int r1 = r0 + 8;
        const int w0 = r0 / 49;
        const int p0 = r0 - w0 * 49;
        const int w1 = r1 / 49;
        const int p1 = r1 - w1 * 49;
#pragma unroll
        for (int j = 0; j < 4; j++) {
            const int n = n0 + wn + j * 8 + 2 * ctid;
            const float bz0 = __ldg(&bias[n]);
            const float bz1 = __ldg(&bias[n + 1]);
            scatter_qkv_bf(w0, p0, n, acc[i][j][0] + bz0, acc[i][j][1] + bz1);
            scatter_qkv_bf(w1, p1, n, acc[i][j][2] + bz0, acc[i][j][3] + bz1);
        }
    }
}

__global__ __launch_bounds__(256) void proj_mma(const float* __restrict__ bias,
                                                float* __restrict__ outp) {
    const int tid = threadIdx.x;
    const int n0 = blockIdx.x * BN;
    const int m0 = blockIdx.y * BM;

    const int warp = tid >> 5;
    const int lane = tid & 31;
    const int wm = (warp >> 2) * 64;
    const int wn = (warp & 3) * 32;

    const int mt0 = (m0 + wm) >> 4;
    const __nv_bfloat16* aH = g_aFh + ((size_t)mt0 * NKC_) * 256 + lane * 8;
    const __nv_bfloat16* aL = g_aFl + ((size_t)mt0 * NKC_) * 256 + lane * 8;

    const int ng0 = (n0 + wn) >> 4;
    const __nv_bfloat16* bH = g_woutFh + (size_t)ng0 * 6144 + lane * 8;
    const __nv_bfloat16* bL = g_woutFl + (size_t)ng0 * 6144 + lane * 8;

    float acc[4][4][4];
#pragma unroll
    for (int i = 0; i < 4; i++)
#pragma unroll
        for (int j = 0; j < 4; j++)
#pragma unroll
            for (int e = 0; e < 4; e++) acc[i][j][e] = 0.f;

#pragma unroll 4
    for (int kt = 0; kt < NKC_; kt++) {
        uint4 ahv[4];
        uint4 alv[4];
#pragma unroll
        for (int i = 0; i < 4; i++) {
            ahv[i] = *(const uint4*)(aH + ((size_t)i * NKC_ + kt) * 256);
            alv[i] = *(const uint4*)(aL + ((size_t)i * NKC_ + kt) * 256);
        }
        const uint4 bh01 = *(const uint4*)(bH + kt * 256);
        const uint4 bh23 = *(const uint4*)(bH + 6144 + kt * 256);
        const uint4 bl01 = *(const uint4*)(bL + kt * 256);
        const uint4 bl23 = *(const uint4*)(bL + 6144 + kt * 256);
        uint32_t bh[4][2];
        uint32_t bl[4][2];
        bh[0][0] = bh01.x; bh[0][1] = bh01.y;
        bh[1][0] = bh01.z; bh[1][1] = bh01.w;
        bh[2][0] = bh23.x; bh[2][1] = bh23.y;
        bh[3][0] = bh23.z; bh[3][1] = bh23.w;
        bl[0][0] = bl01.x; bl[0][1] = bl01.y;
        bl[1][0] = bl01.z; bl[1][1] = bl01.w;
        bl[2][0] = bl23.x; bl[2][1] = bl23.y;
        bl[3][0] = bl23.z; bl[3][1] = bl23.w;

#pragma unroll
        for (int i = 0; i < 4; i++) {
            const uint32_t* ah = (const uint32_t*)&ahv[i];
            const uint32_t* al = (const uint32_t*)&alv[i];
#pragma unroll
            for (int j = 0; j < 4; j++) {
                mma16816(acc[i][j], ah, bh[j]);
                mma16816(acc[i][j], ah, bl[j]);
                mma16816(acc[i][j], al, bh[j]);
            }
        }
    }

    const int gid = lane >> 2;
    const int ctid = lane & 3;
#pragma unroll
    for (int i = 0; i < 4; i++) {
        const int r0 = m0 + wm + i * 16 + gid;
        const int r1 = r0 + 8;
        const int x0 = token_to_xoff(r0);
        const int x1 = token_to_xoff(r1);
#pragma unroll
        for (int j = 0; j < 4; j++) {
            const int n = n0 + wn + j * 8 + 2 * ctid;
            const float bz0 = __ldg(&bias[n]);
            const float bz1 = __ldg(&bias[n + 1]);
            float2 v0;
            float2 v1;
            v0.x = acc[i][j][0] + bz0;
            v0.y = acc[i][j][1] + bz1;
            v1.x = acc[i][j][2] + bz0;
            v1.y = acc[i][j][3] + bz1;
            *(float2*)&outp[x0 + n] = v0;
            *(float2*)&outp[x1 + n] = v1;
        }
    }
}

// ---------------------------------------------------------------------------
// Attention (proven, unchanged)
// ---------------------------------------------------------------------------
__device__ __forceinline__ void ldm4(uint32_t* r, const __nv_bfloat16* p) {
    uint32_t addr = (uint32_t)__cvta_generic_to_shared(p);
    asm volatile("ldmatrix.sync.aligned.m8n8.x4.shared.b16 {%0,%1,%2,%3}, [%4];"
                 : "=r"(r[0]), "=r"(r[1]), "=r"(r[2]), "=r"(r[3]) : "r"(addr));
}

#define QKS 40
#define VTS 72

__global__ __launch_bounds__(128, 6) void attn_mma(const float* __restrict__ rel_pos) {
    const int wh = blockIdx.x;
    const int h  = wh % NH_;
    const int w  = wh / NH_;
    const int tid = threadIdx.x;
    const int warp = tid >> 5;
    const int lane = tid & 31;

    __shared__ __nv_bfloat16 Qh[64 * QKS];
    __shared__ __nv_bfloat16 Ql[64 * QKS];
    __shared__ __nv_bfloat16 Kh[64 * QKS];
    __shared__ __nv_bfloat16 Kl[64 * QKS];
    __shared__ __nv_bfloat16 Vth[32 * VTS];
    __shared__ __nv_bfloat16 Vtl[32 * VTS];
    __shared__ float Bb[169];

    const int base = wh * (P_ * HD_);

    for (int e = tid; e < 32 * VTS; e += 128) {
        ((ushort*)Vth)[e] = 0;
        ((ushort*)Vtl)[e] = 0;
    }
    __syncthreads();

    for (int e = tid; e < 49 * 4; e += 128) {
        const int p = e >> 2;
        const int ch = (e & 3) * 8;
        *(uint4*)&Qh[p * QKS + ch] = *(const uint4*)&g_qh[base + p * 32 + ch];
        *(uint4*)&Ql[p * QKS + ch] = *(const uint4*)&g_ql[base + p * 32 + ch];
        *(uint4*)&Kh[p * QKS + ch] = *(const uint4*)&g_kh[base + p * 32 + ch];
        *(uint4*)&Kl[p * QKS + ch] = *(const uint4*)&g_kl[base + p * 32 + ch];
        const uint4 vh = *(const uint4*)&g_vh[base + p * 32 + ch];
        const uint4 vl = *(const uint4*)&g_vl[base + p * 32 + ch];
        const uint32_t* vhw = (const uint32_t*)&vh;
        const uint32_t* vlw = (const uint32_t*)&vl;
#pragma unroll
        for (int i = 0; i < 4; i++) {
            const int d = ch + 2 * i;
            ((ushort*)Vth)[d * VTS + p]       = (ushort)(vhw[i] & 0xffff);
            ((ushort*)Vth)[(d + 1) * VTS + p] = (ushort)(vhw[i] >> 16);
            ((ushort*)Vtl)[d * VTS + p]       = (ushort)(vlw[i] & 0xffff);
            ((ushort*)Vtl)[(d + 1) * VTS + p] = (ushort)(vlw[i] >> 16);
        }
    }
    for (int e = tid; e < 169; e += 128) Bb[e] = rel_pos[h * 169 + e];
    __syncthreads();

    const int grp = lane >> 3;
    const int lr = lane & 7;
    const int a_r = (grp & 1) * 8 + lr;
    const int a_k = (grp >> 1) * 8;
    const int b_r = (grp >> 1) * 8 + lr;
    const int b_k = (grp & 1) * 8;
    const int gid = lane >> 2;
    const int ctid = lane & 3;

    float accS[8][4];
#pragma unroll
    for (int t = 0; t < 8; t++)
#pragma unroll
        for (int e = 0; e < 4; e++) accS[t][e] = 0.f;

#pragma unroll
    for (int ko = 0; ko < 32; ko += 16) {
        uint32_t ah[4];
        uint32_t al[4];
        ldm4(ah, &Qh[(warp * 16 + a_r) * QKS + a_k + ko]);
        ldm4(al, &Ql[(warp * 16 + a_r) * QKS + a_k + ko]);
#pragma unroll
        for (int jt = 0; jt < 4; jt++) {
            uint32_t th[4];
            uint32_t tl[4];
            ldm4(th, &Kh[(jt * 16 + b_r) * QKS + b_k + ko]);
            ldm4(tl, &Kl[(jt * 16 + b_r) * QKS + b_k + ko]);
            uint32_t bh0[2]; bh0[0] = th[0]; bh0[1] = th[1];
            uint32_t bh1[2]; bh1[0] = th[2]; bh1[1] = th[3];
            uint32_t bl0[2]; bl0[0] = tl[0]; bl0[1] = tl[1];
            uint32_t bl1[2]; bl1[0] = tl[2]; bl1[1] = tl[3];
            mma16816(accS[jt * 2],     ah, bh0);
            mma16816(accS[jt * 2],     ah, bl0);
            mma16816(accS[jt * 2],     al, bh0);
            mma16816(accS[jt * 2 + 1], ah, bh1);
            mma16816(accS[jt * 2 + 1], ah, bl1);
            mma16816(accS[jt * 2 + 1], al, bh1);
        }
    }

    const float scale = 0.17677669529663687f;
    const int i0 = warp * 16 + gid;
    const int i1 = i0 + 8;
    const int i0d = i0 / 7;
    const int i0m = i0 % 7;
    const int i1d = i1 / 7;
    const int i1m = i1 % 7;
    const bool v0row = (i0 < 49);
    const bool v1row = (i1 < 49);

    float m0 = -1e30f;
    float m1 = -1e30f;
#pragma unroll
    for (int t = 0; t < 8; t++) {
        const int j0 = t * 8 + 2 * ctid;
        const int j1 = j0 + 1;
        const int jd0 = j0 / 7, jm0 = j0 % 7;
        const int jd1 = j1 / 7, jm1 = j1 % 7;
        float s00 = accS[t][0] * scale;
        float s01 = accS[t][1] * scale;
        float s10 = accS[t][2] * scale;
        float s11 = accS[t][3] * scale;
        if (v0row && j0 < 49) s00 += Bb[(i0d - jd0 + 6) * 13 + (i0m - jm0 + 6)];
        if (v0row && j1 < 49) s01 += Bb[(i0d - jd1 + 6) * 13 + (i0m - jm1 + 6)];
        if (v1row && j0 < 49) s10 += Bb[(i1d - jd0 + 6) * 13 + (i1m - jm0 + 6)];
        if (v1row && j1 < 49) s11 += Bb[(i1d - jd1 + 6) * 13 + (i1m - jm1 + 6)];
        if (j0 >= 49) { s00 = -1e30f; s10 = -1e30f; }
        if (j1 >= 49) { s01 = -1e30f; s11 = -1e30f; }
        accS[t][0] = s00;
        accS[t][1] = s01;
        accS[t][2] = s10;
        accS[t][3] = s11;
        m0 = fmaxf(m0, fmaxf(s00, s01));
        m1 = fmaxf(m1, fmaxf(s10, s11));
    }
    m0 = fmaxf(m0, __shfl_xor_sync(~0u, m0, 1));
    m0 = fmaxf(m0, __shfl_xor_sync(~0u, m0, 2));
    m1 = fmaxf(m1, __shfl_xor_sync(~0u, m1, 1));
    m1 = fmaxf(m1, __shfl_xor_sync(~0u, m1, 2));

    float sum0 = 0.f;
    float sum1 = 0.f;
#pragma unroll
    for (int t = 0; t < 8; t++) {
        float e00 = __expf(accS[t][0] - m0);
        float e01 = __expf(accS[t][1] - m0);
        float e10 = __expf(accS[t][2] - m1);
        float e11 = __expf(accS[t][3] - m1);
        accS[t][0] = e00;
        accS[t][1] = e01;
        accS[t][2] = e10;
        accS[t][3] = e11;
        sum0 += e00 + e01;
        sum1 += e10 + e11;
    }
    sum0 += __shfl_xor_sync(~0u, sum0, 1);
    sum0 += __shfl_xor_sync(~0u, sum0, 2);
    sum1 += __shfl_xor_sync(~0u, sum1, 1);
    sum1 += __shfl_xor_sync(~0u, sum1, 2);
    const float inv0 = 1.f / sum0;
    const float inv1 = 1.f / sum1;
#pragma unroll
    for (int t = 0; t < 8; t++) {
        accS[t][0] *= inv0;
        accS[t][1] *= inv0;
        accS[t][2] *= inv1;
        accS[t][3] *= inv1;
    }

    uint32_t pah[4][4];
    uint32_t pal[4][4];
#pragma unroll
    for (int s = 0; s < 4; s++) {
        const int te = 2 * s;
        const int to = 2 * s + 1;
        pah[s][0] = pack_hi2(accS[te][0], accS[te][1]);
        pal[s][0] = pack_lo2(accS[te][0], accS[te][1]);
        pah[s][1] = pack_hi2(accS[te][2], accS[te][3]);
        pal[s][1] = pack_lo2(accS[te][2], accS[te][3]);
        pah[s][2] = pack_hi2(accS[to][0], accS[to][1]);
        pal[s][2] = pack_lo2(accS[to][0], accS[to][1]);
        pah[s][3] = pack_hi2(accS[to][2], accS[to][3]);
        pal[s][3] = pack_lo2(accS[to][2], accS[to][3]);
    }

    float accO[4][4];
#pragma unroll
    for (int t = 0; t < 4; t++)
#pragma unroll
        for (int e = 0; e < 4; e++) accO[t][e] = 0.f;

#pragma unroll
    for (int s = 0; s < 4; s++) {
#pragma unroll
        for (int nb = 0; nb < 2; nb++) {
            uint32_t th[4];
            uint32_t tl[4];
            ldm4(th, &Vth[(nb * 16 + b_r) * VTS + b_k + s * 16]);
            ldm4(tl, &Vtl[(nb * 16 + b_r) * VTS + b_k + s * 16]);
            uint32_t bh0[2]; bh0[0] = th[0]; bh0[1] = th[1];
            uint32_t bh1[2]; bh1[0] = th[2]; bh1[1] = th[3];
            uint32_t bl0[2]; bl0[0] = tl[0]; bl0[1] = tl[1];
            uint32_t bl1[2]; bl1[0] = tl[2]; bl1[1] = tl[3];
            mma16816(accO[nb * 2],     pah[s], bh0);
            mma16816(accO[nb * 2],     pah[s], bl0);
            mma16816(accO[nb * 2],     pal[s], bh0);
            mma16816(accO[nb * 2 + 1], pah[s], bh1);
            mma16816(accO[nb * 2 + 1], pah[s], bl1);
            mma16816(accO[nb * 2 + 1], pal[s], bh1);
        }
    }

    if (v0row) {
        float* dst = g_attn + (size_t)(w * P_ + i0) * C_ + h * HD_;
#pragma unroll
        for (int nt = 0; nt < 4; nt++) {
            float2 v;
            v.x = accO[nt][0];
            v.y = accO[nt][1];
            *(float2*)&dst[nt * 8 + 2 * ctid] = v;
        }
    }
    if (v1row) {
        float* dst = g_attn + (size_t)(w * P_ + i1) * C_ + h * HD_;
#pragma unroll
        for (int nt = 0; nt < 4; nt++) {
            float2 v;
            v.x = accO[nt][2];
            v.y = accO[nt][3];
            *(float2*)&dst[nt * 8 + 2 * ctid] = v;
        }
    }
}

// ---------------------------------------------------------------------------
extern "C" void kernel_launch(void* const* d_in, const int* in_sizes, int n_in,
                              void* d_out, int out_size) {
    (void)in_sizes; (void)n_in; (void)out_size;
    const float* x      = (const float*)d_in[0];
    const float* w_qkv  = (const float*)d_in[1];
    const float* b_qkv  = (const float*)d_in[2];
    const float* relpos = (const float*)d_in[3];
    const float* w_out  = (const float*)d_in[4];
    const float* b_out  = (const float*)d_in[5];
    float* out = (float*)d_out;

    prep_wF<<<2304, 256>>>(w_qkv, w_out);
    prep_xF<<<NMT_ * NKC_ * 32 / 256, 256>>>(x);   // 18816 blocks

    dim3 g1(QKVN_ / BN, TOK_ / BM);   // 9 x 784
    qkv_mma<<<g1, 256>>>(b_qkv);

    attn_mma<<<BW_ * NH_, 128>>>(relpos);

    prep_aF<<<NMT_ * NKC_ * 32 / 256, 256>>>();

    dim3 g3(C_ / BN, TOK_ / BM);      // 3 x 784
    proj_mma<<<g3, 256>>>(b_out, out);
}

// round 15
// speedup vs baseline: 1.6011x; 1.6011x over previous
#include <cuda_runtime.h>
#include <cuda_bf16.h>
#include <stdint.h>

#define C_    384
#define NH_   12
#define HD_   32
#define P_    49
#define BW_   2048
#define TOK_  100352
#define QKVN_ 1152
#define NKC_  24
#define SCALE_ 0.17677669529663687f

#define WQKV_FSZ (72 * NKC_ * 32 * 8)
#define WOUT_FSZ (24 * NKC_ * 32 * 8)

__device__ float g_attn[TOK_ * C_];
__device__ __nv_bfloat16 g_qh[BW_ * NH_ * P_ * HD_];
__device__ __nv_bfloat16 g_ql[BW_ * NH_ * P_ * HD_];
__device__ __nv_bfloat16 g_kh[BW_ * NH_ * P_ * HD_];
__device__ __nv_bfloat16 g_kl[BW_ * NH_ * P_ * HD_];
__device__ __nv_bfloat16 g_vh[BW_ * NH_ * P_ * HD_];
__device__ __nv_bfloat16 g_vl[BW_ * NH_ * P_ * HD_];
__device__ __nv_bfloat16 g_wqkvFh[WQKV_FSZ];
__device__ __nv_bfloat16 g_wqkvFl[WQKV_FSZ];
__device__ __nv_bfloat16 g_woutFh[WOUT_FSZ];
__device__ __nv_bfloat16 g_woutFl[WOUT_FSZ];

__device__ __forceinline__ int token_to_xoff(int t) {
    int b  = t / 3136;
    int r  = t - b * 3136;
    int w  = r / 49;
    int pp = r - w * 49;
    int wi = w >> 3, wj = w & 7;
    int pi = pp / 7, pj = pp - pi * 7;
    return ((b * 56 + wi * 7 + pi) * 56 + (wj * 7 + pj)) * 384;
}

__global__ void prep_wF(const float* __restrict__ wqkv, const float* __restrict__ wout) {
    const int idx = blockIdx.x * 256 + threadIdx.x;
    if (idx < WQKV_FSZ) {
        const int j = idx & 7;
        int tmp = idx >> 3;
        const int lane = tmp & 31;
        tmp >>= 5;
        const int kc = tmp % NKC_;
        const int ng = tmp / NKC_;
        const int pr = j >> 2;
        const int rg = (j >> 1) & 1;
        const int je = j & 1;
        const int n = ng * 16 + (lane >> 2) + pr * 8;
        const int k = kc * 16 + rg * 8 + (lane & 3) * 2 + je;
        const float v = wqkv[k * QKVN_ + n];
        const __nv_bfloat16 h = __float2bfloat16(v);
        g_wqkvFh[idx] = h;
        g_wqkvFl[idx] = __float2bfloat16(v - __bfloat162float(h));
    } else {
        const int i2 = idx - WQKV_FSZ;
        if (i2 < WOUT_FSZ) {
            const int j = i2 & 7;
            int tmp = i2 >> 3;
            const int lane = tmp & 31;
            tmp >>= 5;
            const int kc = tmp % NKC_;
            const int ng = tmp / NKC_;
            const int pr = j >> 2;
            const int rg = (j >> 1) & 1;
            const int je = j & 1;
            const int n = ng * 16 + (lane >> 2) + pr * 8;
            const int k = kc * 16 + rg * 8 + (lane & 3) * 2 + je;
            const float v = wout[k * C_ + n];
            const __nv_bfloat16 h = __float2bfloat16(v);
            g_woutFh[i2] = h;
            g_woutFl[i2] = __float2bfloat16(v - __bfloat162float(h));
        }
    }
}

__device__ __forceinline__ void ldm4(uint32_t* r, const __nv_bfloat16* p) {
    uint32_t addr = (uint32_t)__cvta_generic_to_shared(p);
    asm volatile("ldmatrix.sync.aligned.m8n8.x4.shared.b16 {%0,%1,%2,%3}, [%4];"
                 : "=r"(r[0]), "=r"(r[1]), "=r"(r[2]), "=r"(r[3]) : "r"(addr));
}
__device__ __forceinline__ void mma16816(float* c, const uint32_t* a, const uint32_t* b) {
    asm volatile("mma.sync.aligned.m16n8k16.row.col.f32.bf16.bf16.f32 "
                 "{%0,%1,%2,%3}, {%4,%5,%6,%7}, {%8,%9}, {%0,%1,%2,%3};"
                 : "+f"(c[0]), "+f"(c[1]), "+f"(c[2]), "+f"(c[3])
                 : "r"(a[0]), "r"(a[1]), "r"(a[2]), "r"(a[3]), "r"(b[0]), "r"(b[1]));
}

__device__ __forceinline__ void split_store8(float4 a, float4 b,
                                             __nv_bfloat16* dh, __nv_bfloat16* dl) {
    float f[8];
    f[0] = a.x; f[1] = a.y; f[2] = a.z; f[3] = a.w;
    f[4] = b.x; f[5] = b.y; f[6] = b.z; f[7] = b.w;
    uint32_t hw[4];
    uint32_t lw[4];
#pragma unroll
    for (int i = 0; i < 4; i++) {
        __nv_bfloat16 h0 = __float2bfloat16(f[2 * i]);
        __nv_bfloat16 h1 = __float2bfloat16(f[2 * i + 1]);
        __nv_bfloat16 l0 = __float2bfloat16(f[2 * i] - __bfloat162float(h0));
        __nv_bfloat16 l1 = __float2bfloat16(f[2 * i + 1] - __bfloat162float(h1));
        hw[i] = (uint32_t)__bfloat16_as_ushort(h0) | ((uint32_t)__bfloat16_as_ushort(h1) << 16);
        lw[i] = (uint32_t)__bfloat16_as_ushort(l0) | ((uint32_t)__bfloat16_as_ushort(l1) << 16);
    }
    uint4 H;
    uint4 L;
    H.x = hw[0]; H.y = hw[1]; H.z = hw[2]; H.w = hw[3];
    L.x = lw[0]; L.y = lw[1]; L.z = lw[2]; L.w = lw[3];
    *(uint4*)dh = H;
    *(uint4*)dl = L;
}

__device__ __forceinline__ uint32_t pack_hi2(float x, float y) {
    __nv_bfloat16 hx = __float2bfloat16(x);
    __nv_bfloat16 hy = __float2bfloat16(y);
    return (uint32_t)__bfloat16_as_ushort(hx) | ((uint32_t)__bfloat16_as_ushort(hy) << 16);
}
__device__ __forceinline__ uint32_t pack_lo2(float x, float y) {
    __nv_bfloat16 hx = __float2bfloat16(x);
    __nv_bfloat16 hy = __float2bfloat16(y);
    __nv_bfloat16 lx = __float2bfloat16(x - __bfloat162float(hx));
    __nv_bfloat16 ly = __float2bfloat16(y - __bfloat162float(hy));
    return (uint32_t)__bfloat16_as_ushort(lx) | ((uint32_t)__bfloat16_as_ushort(ly) << 16);
}

// scale folded into Q at write time
__device__ __forceinline__ void scatter_qkv_bf(int w, int pp, int n, float vx, float vy) {
    int which = n / C_;
    int nn = n - which * C_;
    int head = nn >> 5;
    int d = nn & 31;
    __nv_bfloat16* dh;
    __nv_bfloat16* dl;
    if (which == 0)      { dh = g_qh; dl = g_ql; vx *= SCALE_; vy *= SCALE_; }
    else if (which == 1) { dh = g_kh; dl = g_kl; }
    else                 { dh = g_vh; dl = g_vl; }
    int off = ((w * NH_ + head) * P_ + pp) * HD_ + d;
    *(uint32_t*)&dh[off] = pack_hi2(vx, vy);
    *(uint32_t*)&dl[off] = pack_lo2(vx, vy);
}

#define BM 128
#define BN 128
#define BK 16
#define BKP 24

// ---------------------------------------------------------------------------
// Kernel 1: QKV GEMM — A via smem pipeline, B frags direct from L2 (R13)
// ---------------------------------------------------------------------------
__global__ __launch_bounds__(256) void qkv_mma(const float* __restrict__ x,
                                               const float* __restrict__ bias) {
    __shared__ __nv_bfloat16 AsH[2][BM][BKP];
    __shared__ __nv_bfloat16 AsL[2][BM][BKP];

    const int tid = threadIdx.x;
    const int n0 = blockIdx.x * BN;
    const int m0 = blockIdx.y * BM;

    const int arow  = tid >> 1;
    const int akoff = (tid & 1) * 8;
    const float* aptr = x + token_to_xoff(m0 + arow) + akoff;

    const int warp = tid >> 5;
    const int lane = tid & 31;
    const int wm = (warp >> 2) * 64;
    const int wn = (warp & 3) * 32;
    const int grp = lane >> 3;
    const int lr = lane & 7;
    const int a_r = (grp & 1) * 8 + lr;
    const int a_k = (grp >> 1) * 8;

    const int ng0 = (n0 + wn) >> 4;
    const __nv_bfloat16* bH = g_wqkvFh + (size_t)ng0 * 6144 + lane * 8;
    const __nv_bfloat16* bL = g_wqkvFl + (size_t)ng0 * 6144 + lane * 8;

    float acc[4][4][4];
#pragma unroll
    for (int i = 0; i < 4; i++)
#pragma unroll
        for (int j = 0; j < 4; j++)
#pragma unroll
            for (int e = 0; e < 4; e++) acc[i][j][e] = 0.f;

    float4 fa0 = *(const float4*)(aptr);
    float4 fa1 = *(const float4*)(aptr + 4);
    split_store8(fa0, fa1, &AsH[0][arow][akoff], &AsL[0][arow][akoff]);
    __syncthreads();

    const int NT = C_ / BK;
    for (int kt = 0; kt < NT; kt++) {
        const int cur = kt & 1;
        if (kt + 1 < NT) {
            const int kg = (kt + 1) * BK;
            fa0 = *(const float4*)(aptr + kg);
            fa1 = *(const float4*)(aptr + kg + 4);
        }

        const uint4 bh01 = *(const uint4*)(bH + kt * 256);
        const uint4 bh23 = *(const uint4*)(bH + 6144 + kt * 256);
        const uint4 bl01 = *(const uint4*)(bL + kt * 256);
        const uint4 bl23 = *(const uint4*)(bL + 6144 + kt * 256);
        uint32_t bh[4][2];
        uint32_t bl[4][2];
        bh[0][0] = bh01.x; bh[0][1] = bh01.y;
        bh[1][0] = bh01.z; bh[1][1] = bh01.w;
        bh[2][0] = bh23.x; bh[2][1] = bh23.y;
        bh[3][0] = bh23.z; bh[3][1] = bh23.w;
        bl[0][0] = bl01.x; bl[0][1] = bl01.y;
        bl[1][0] = bl01.z; bl[1][1] = bl01.w;
        bl[2][0] = bl23.x; bl[2][1] = bl23.y;
        bl[3][0] = bl23.z; bl[3][1] = bl23.w;

        uint32_t ah[4][4];
        uint32_t al[4][4];
#pragma unroll
        for (int i = 0; i < 4; i++) {
            ldm4(ah[i], &AsH[cur][wm + i * 16 + a_r][a_k]);
            ldm4(al[i], &AsL[cur][wm + i * 16 + a_r][a_k]);
        }

#pragma unroll
        for (int i = 0; i < 4; i++)
#pragma unroll
            for (int j = 0; j < 4; j++) {
                mma16816(acc[i][j], ah[i], bh[j]);
                mma16816(acc[i][j], ah[i], bl[j]);
                mma16816(acc[i][j], al[i], bh[j]);
            }

        if (kt + 1 < NT) {
            const int nxt = cur ^ 1;
            split_store8(fa0, fa1, &AsH[nxt][arow][akoff], &AsL[nxt][arow][akoff]);
            __syncthreads();
        }
    }

    const int gid = lane >> 2;
    const int ctid = lane & 3;
#pragma unroll
    for (int i = 0; i < 4; i++) {
        const int r0 = m0 + wm + i * 16 + gid;
        const int r1 = r0 + 8;
        const int w0 = r0 / 49;
        const int p0 = r0 - w0 * 49;
        const int w1 = r1 / 49;
        const int p1 = r1 - w1 * 49;
#pragma unroll
        for (int j = 0; j < 4; j++) {
            const int n = n0 + wn + j * 8 + 2 * ctid;
            const float bz0 = __ldg(&bias[n]);
            const float bz1 = __ldg(&bias[n + 1]);
            scatter_qkv_bf(w0, p0, n, acc[i][j][0] + bz0, acc[i][j][1] + bz1);
            scatter_qkv_bf(w1, p1, n, acc[i][j][2] + bz0, acc[i][j][3] + bz1);
        }
    }
}

// ---------------------------------------------------------------------------
// Kernel 3: proj GEMM (R13)
// ---------------------------------------------------------------------------
__global__ __launch_bounds__(256) void proj_mma(const float* __restrict__ bias,
                                                float* __restrict__ outp) {
    __shared__ __nv_bfloat16 AsH[2][BM][BKP];
    __shared__ __nv_bfloat16 AsL[2][BM][BKP];

    const int tid = threadIdx.x;
    const int n0 = blockIdx.x * BN;
    const int m0 = blockIdx.y * BM;

    const int arow  = tid >> 1;
    const int akoff = (tid & 1) * 8;
    const float* aptr = g_attn + (size_t)(m0 + arow) * C_ + akoff;

    const int warp = tid >> 5;
    const int lane = tid & 31;
    const int wm = (warp >> 2) * 64;
    const int wn = (warp & 3) * 32;
    const int grp = lane >> 3;
    const int lr = lane & 7;
    const int a_r = (grp & 1) * 8 + lr;
    const int a_k = (grp >> 1) * 8;

    const int ng0 = (n0 + wn) >> 4;
    const __nv_bfloat16* bH = g_woutFh + (size_t)ng0 * 6144 + lane * 8;
    const __nv_bfloat16* bL = g_woutFl + (size_t)ng0 * 6144 + lane * 8;

    float acc[4][4][4];
#pragma unroll
    for (int i = 0; i < 4; i++)
#pragma unroll
        for (int j = 0; j < 4; j++)
#pragma unroll
            for (int e = 0; e < 4; e++) acc[i][j][e] = 0.f;

    float4 fa0 = *(const float4*)(aptr);
    float4 fa1 = *(const float4*)(aptr + 4);
    split_store8(fa0, fa1, &AsH[0][arow][akoff], &AsL[0][arow][akoff]);
    __syncthreads();

    const int NT = C_ / BK;
    for (int kt = 0; kt < NT; kt++) {
        const int cur = kt & 1;
        if (kt + 1 < NT) {
            const int kg = (kt + 1) * BK;
            fa0 = *(const float4*)(aptr + kg);
            fa1 = *(const float4*)(aptr + kg + 4);
        }

        const uint4 bh01 = *(const uint4*)(bH + kt * 256);
        const uint4 bh23 = *(const uint4*)(bH + 6144 + kt * 256);
        const uint4 bl01 = *(const uint4*)(bL + kt * 256);
        const uint4 bl23 = *(const uint4*)(bL + 6144 + kt * 256);
        uint32_t bh[4][2];
        uint32_t bl[4][2];
        bh[0][0] = bh01.x; bh[0][1] = bh01.y;
        bh[1][0] = bh01.z; bh[1][1] = bh01.w;
        bh[2][0] = bh23.x; bh[2][1] = bh23.y;
        bh[3][0] = bh23.z; bh[3][1] = bh23.w;
        bl[0][0] = bl01.x; bl[0][1] = bl01.y;
        bl[1][0] = bl01.z; bl[1][1] = bl01.w;
        bl[2][0] = bl23.x; bl[2][1] = bl23.y;
        bl[3][0] = bl23.z; bl[3][1] = bl23.w;

        uint32_t ah[4][4];
        uint32_t al[4][4];
#pragma unroll
        for (int i = 0; i < 4; i++) {
            ldm4(ah[i], &AsH[cur][wm + i * 16 + a_r][a_k]);
            ldm4(al[i], &AsL[cur][wm + i * 16 + a_r][a_k]);
        }

#pragma unroll
        for (int i = 0; i < 4; i++)
#pragma unroll
            for (int j = 0; j < 4; j++) {
                mma16816(acc[i][j], ah[i], bh[j]);
                mma16816(acc[i][j], ah[i], bl[j]);
                mma16816(acc[i][j], al[i], bh[j]);
            }

        if (kt + 1 < NT) {
            const int nxt = cur ^ 1;
            split_store8(fa0, fa1, &AsH[nxt][arow][akoff], &AsL[nxt][arow][akoff]);
            __syncthreads();
        }
    }

    const int gid = lane >> 2;
    const int ctid = lane & 3;
#pragma unroll
    for (int i = 0; i < 4; i++) {
        const int r0 = m0 + wm + i * 16 + gid;
        const int r1 = r0 + 8;
        const int x0 = token_to_xoff(r0);
        const int x1 = token_to_xoff(r1);
#pragma unroll
        for (int j = 0; j < 4; j++) {
            const int n = n0 + wn + j * 8 + 2 * ctid;
            const float bz0 = __ldg(&bias[n]);
            const float bz1 = __ldg(&bias[n + 1]);
            float2 v0;
            float2 v1;
            v0.x = acc[i][j][0] + bz0;
            v0.y = acc[i][j][1] + bz1;
            v1.x = acc[i][j][2] + bz0;
            v1.y = acc[i][j][3] + bz1;
            *(float2*)&outp[x0 + n] = v0;
            *(float2*)&outp[x1 + n] = v1;
        }
    }
}

// ---------------------------------------------------------------------------
// Kernel 2: attention — scale pre-folded into Q
// ---------------------------------------------------------------------------
#define QKS 40
#define VTS 72

__global__ __launch_bounds__(128, 6) void attn_mma(const float* __restrict__ rel_pos) {
    const int wh = blockIdx.x;
    const int h  = wh % NH_;
    const int w  = wh / NH_;
    const int tid = threadIdx.x;
    const int warp = tid >> 5;
    const int lane = tid & 31;

    __shared__ __nv_bfloat16 Qh[64 * QKS];
    __shared__ __nv_bfloat16 Ql[64 * QKS];
    __shared__ __nv_bfloat16 Kh[64 * QKS];
    __shared__ __nv_bfloat16 Kl[64 * QKS];
    __shared__ __nv_bfloat16 Vth[32 * VTS];
    __shared__ __nv_bfloat16 Vtl[32 * VTS];
    __shared__ float Bb[169];

    const int base = wh * (P_ * HD_);

    for (int e = tid; e < 32 * VTS; e += 128) {
        ((ushort*)Vth)[e] = 0;
        ((ushort*)Vtl)[e] = 0;
    }
    __syncthreads();

    for (int e = tid; e < 49 * 4; e += 128) {
        const int p = e >> 2;
        const int ch = (e & 3) * 8;
        *(uint4*)&Qh[p * QKS + ch] = *(const uint4*)&g_qh[base + p * 32 + ch];
        *(uint4*)&Ql[p * QKS + ch] = *(const uint4*)&g_ql[base + p * 32 + ch];
        *(uint4*)&Kh[p * QKS + ch] = *(const uint4*)&g_kh[base + p * 32 + ch];
        *(uint4*)&Kl[p * QKS + ch] = *(const uint4*)&g_kl[base + p * 32 + ch];
        const uint4 vh = *(const uint4*)&g_vh[base + p * 32 + ch];
        const uint4 vl = *(const uint4*)&g_vl[base + p * 32 + ch];
        const uint32_t* vhw = (const uint32_t*)&vh;
        const uint32_t* vlw = (const uint32_t*)&vl;
#pragma unroll
        for (int i = 0; i < 4; i++) {
            const int d = ch + 2 * i;
            ((ushort*)Vth)[d * VTS + p]       = (ushort)(vhw[i] & 0xffff);
            ((ushort*)Vth)[(d + 1) * VTS + p] = (ushort)(vhw[i] >> 16);
            ((ushort*)Vtl)[d * VTS + p]       = (ushort)(vlw[i] & 0xffff);
            ((ushort*)Vtl)[(d + 1) * VTS + p] = (ushort)(vlw[i] >> 16);
        }
    }
    for (int e = tid; e < 169; e += 128) Bb[e] = rel_pos[h * 169 + e];
    __syncthreads();

    const int grp = lane >> 3;
    const int lr = lane & 7;
    const int a_r = (grp & 1) * 8 + lr;
    const int a_k = (grp >> 1) * 8;
    const int b_r = (grp >> 1) * 8 + lr;
    const int b_k = (grp & 1) * 8;
    const int gid = lane >> 2;
    const int ctid = lane & 3;

    float accS[8][4];
#pragma unroll
    for (int t = 0; t < 8; t++)
#pragma unroll
        for (int e = 0; e < 4; e++) accS[t][e] = 0.f;

#pragma unroll
    for (int ko = 0; ko < 32; ko += 16) {
        uint32_t ah[4];
        uint32_t al[4];
        ldm4(ah, &Qh[(warp * 16 + a_r) * QKS + a_k + ko]);
        ldm4(al, &Ql[(warp * 16 + a_r) * QKS + a_k + ko]);
#pragma unroll
        for (int jt = 0; jt < 4; jt++) {
            uint32_t th[4];
            uint32_t tl[4];
            ldm4(th, &Kh[(jt * 16 + b_r) * QKS + b_k + ko]);
            ldm4(tl, &Kl[(jt * 16 + b_r) * QKS + b_k + ko]);
            uint32_t bh0[2]; bh0[0] = th[0]; bh0[1] = th[1];
            uint32_t bh1[2]; bh1[0] = th[2]; bh1[1] = th[3];
            uint32_t bl0[2]; bl0[0] = tl[0]; bl0[1] = tl[1];
            uint32_t bl1[2]; bl1[0] = tl[2]; bl1[1] = tl[3];
            mma16816(accS[jt * 2],     ah, bh0);
            mma16816(accS[jt * 2],     ah, bl0);
            mma16816(accS[jt * 2],     al, bh0);
            mma16816(accS[jt * 2 + 1], ah, bh1);
            mma16816(accS[jt * 2 + 1], ah, bl1);
            mma16816(accS[jt * 2 + 1], al, bh1);
        }
    }

    const int i0 = warp * 16 + gid;
    const int i1 = i0 + 8;
    const int i0d = i0 / 7;
    const int i0m = i0 % 7;
    const int i1d = i1 / 7;
    const int i1m = i1 % 7;
    const bool v0row = (i0 < 49);
    const bool v1row = (i1 < 49);

    float m0 = -1e30f;
    float m1 = -1e30f;
#pragma unroll
    for (int t = 0; t < 8; t++) {
        const int j0 = t * 8 + 2 * ctid;
        const int j1 = j0 + 1;
        const int jd0 = j0 / 7, jm0 = j0 % 7;
        const int jd1 = j1 / 7, jm1 = j1 % 7;
        float s00 = accS[t][0];
        float s01 = accS[t][1];
        float s10 = accS[t][2];
        float s11 = accS[t][3];
        if (v0row && j0 < 49) s00 += Bb[(i0d - jd0 + 6) * 13 + (i0m - jm0 + 6)];
        if (v0row && j1 < 49) s01 += Bb[(i0d - jd1 + 6) * 13 + (i0m - jm1 + 6)];
        if (v1row && j0 < 49) s10 += Bb[(i1d - jd0 + 6) * 13 + (i1m - jm0 + 6)];
        if (v1row && j1 < 49) s11 += Bb[(i1d - jd1 + 6) * 13 + (i1m - jm1 + 6)];
        if (j0 >= 49) { s00 = -1e30f; s10 = -1e30f; }
        if (j1 >= 49) { s01 = -1e30f; s11 = -1e30f; }
        accS[t][0] = s00;
        accS[t][1] = s01;
        accS[t][2] = s10;
        accS[t][3] = s11;
        m0 = fmaxf(m0, fmaxf(s00, s01));
        m1 = fmaxf(m1, fmaxf(s10, s11));
    }
    m0 = fmaxf(m0, __shfl_xor_sync(~0u, m0, 1));
    m0 = fmaxf(m0, __shfl_xor_sync(~0u, m0, 2));
    m1 = fmaxf(m1, __shfl_xor_sync(~0u, m1, 1));
    m1 = fmaxf(m1, __shfl_xor_sync(~0u, m1, 2));

    float sum0 = 0.f;
    float sum1 = 0.f;
#pragma unroll
    for (int t = 0; t < 8; t++) {
        float e00 = __expf(accS[t][0] - m0);
        float e01 = __expf(accS[t][1] - m0);
        float e10 = __expf(accS[t][2] - m1);
        float e11 = __expf(accS[t][3] - m1);
        accS[t][0] = e00;
        accS[t][1] = e01;
        accS[t][2] = e10;
        accS[t][3] = e11;
        sum0 += e00 + e01;
        sum1 += e10 + e11;
    }
    sum0 += __shfl_xor_sync(~0u, sum0, 1);
    sum0 += __shfl_xor_sync(~0u, sum0, 2);
    sum1 += __shfl_xor_sync(~0u, sum1, 1);
    sum1 += __shfl_xor_sync(~0u, sum1, 2);
    const float inv0 = 1.f / sum0;
    const float inv1 = 1.f / sum1;
#pragma unroll
    for (int t = 0; t < 8; t++) {
        accS[t][0] *= inv0;
        accS[t][1] *= inv0;
        accS[t][2] *= inv1;
        accS[t][3] *= inv1;
    }

    uint32_t pah[4][4];
    uint32_t pal[4][4];
#pragma unroll
    for (int s = 0; s < 4; s++) {
        const int te = 2 * s;
        const int to = 2 * s + 1;
        pah[s][0] = pack_hi2(accS[te][0], accS[te][1]);
        pal[s][0] = pack_lo2(accS[te][0], accS[te][1]);
        pah[s][1] = pack_hi2(accS[te][2], accS[te][3]);
        pal[s][1] = pack_lo2(accS[te][2], accS[te][3]);
        pah[s][2] = pack_hi2(accS[to][0], accS[to][1]);
        pal[s][2] = pack_lo2(accS[to][0], accS[to][1]);
        pah[s][3] = pack_hi2(accS[to][2], accS[to][3]);
        pal[s][3] = pack_lo2(accS[to][2], accS[to][3]);
    }

    float accO[4][4];
#pragma unroll
    for (int t = 0; t < 4; t++)
#pragma unroll
        for (int e = 0; e < 4; e++) accO[t][e] = 0.f;

#pragma unroll
    for (int s = 0; s < 4; s++) {
#pragma unroll
        for (int nb = 0; nb < 2; nb++) {
            uint32_t th[4];
            uint32_t tl[4];
            ldm4(th, &Vth[(nb * 16 + b_r) * VTS + b_k + s * 16]);
            ldm4(tl, &Vtl[(nb * 16 + b_r) * VTS + b_k + s * 16]);
            uint32_t bh0[2]; bh0[0] = th[0]; bh0[1] = th[1];
            uint32_t bh1[2]; bh1[0] = th[2]; bh1[1] = th[3];
            uint32_t bl0[2]; bl0[0] = tl[0]; bl0[1] = tl[1];
            uint32_t bl1[2]; bl1[0] = tl[2]; bl1[1] = tl[3];
            mma16816(accO[nb * 2],     pah[s], bh0);
            mma16816(accO[nb * 2],     pah[s], bl0);
            mma16816(accO[nb * 2],     pal[s], bh0);
            mma16816(accO[nb * 2 + 1], pah[s], bh1);
            mma16816(accO[nb * 2 + 1], pah[s], bl1);
            mma16816(accO[nb * 2 + 1], pal[s], bh1);
        }
    }

    if (v0row) {
        float* dst = g_attn + (size_t)(w * P_ + i0) * C_ + h * HD_;
#pragma unroll
        for (int nt = 0; nt < 4; nt++) {
            float2 v;
            v.x = accO[nt][0];
            v.y = accO[nt][1];
            *(float2*)&dst[nt * 8 + 2 * ctid] = v;
        }
    }
    if (v1row) {
        float* dst = g_attn + (size_t)(w * P_ + i1) * C_ + h * HD_;
#pragma unroll
        for (int nt = 0; nt < 4; nt++) {
            float2 v;
            v.x = accO[nt][2];
            v.y = accO[nt][3];
            *(float2*)&dst[nt * 8 + 2 * ctid] = v;
        }
    }
}

// ---------------------------------------------------------------------------
extern "C" void kernel_launch(void* const* d_in, const int* in_sizes, int n_in,
                              void* d_out, int out_size) {
    (void)in_sizes; (void)n_in; (void)out_size;
    const float* x      = (const float*)d_in[0];
    const float* w_qkv  = (const float*)d_in[1];
    const float* b_qkv  = (const float*)d_in[2];
    const float* relpos = (const float*)d_in[3];
    const float* w_out  = (const float*)d_in[4];
    const float* b_out  = (const float*)d_in[5];
    float* out = (float*)d_out;

    prep_wF<<<2304, 256>>>(w_qkv, w_out);

    dim3 g1(QKVN_ / BN, TOK_ / BM);   // 9 x 784, n fastest
    qkv_mma<<<g1, 256>>>(x, b_qkv);

    attn_mma<<<BW_ * NH_, 128>>>(relpos);

    dim3 g3(C_ / BN, TOK_ / BM);      // 3 x 784
    proj_mma<<<g3, 256>>>(b_out, out);
}